// round 10
// baseline (speedup 1.0000x reference)
#include <cuda_runtime.h>
#include <cuda_fp16.h>
#include <cuda_bf16.h>
#include <cstdint>

#define NUM_NETS_MAX 2000000
#define TILE 1024           // pins per tile (4KB per array per tile)
#define STAGES 2

// Per-net accumulators packed as 2x f16x2 in 8 bytes:
//   .x = half2{exp(+x/g), exp(-x/g)}, .y = half2{exp(+y/g), exp(-y/g)}
// Zero at module load; nets kernel re-zeroes after consuming each slot.
__device__ uint2 g_net_sums_h[NUM_NETS_MAX];

// ---------------------------------------------------------------------------
// mbarrier / bulk-copy helpers
// ---------------------------------------------------------------------------
__device__ __forceinline__ uint32_t smem_u32(const void* p) {
    return (uint32_t)__cvta_generic_to_shared(p);
}
__device__ __forceinline__ void mbar_init(uint32_t a, uint32_t count) {
    asm volatile("mbarrier.init.shared.b64 [%0], %1;" :: "r"(a), "r"(count) : "memory");
}
__device__ __forceinline__ void mbar_expect_tx(uint32_t a, uint32_t bytes) {
    asm volatile("mbarrier.arrive.expect_tx.shared.b64 _, [%0], %1;"
                 :: "r"(a), "r"(bytes) : "memory");
}
__device__ __forceinline__ void mbar_arrive(uint32_t a) {
    asm volatile("mbarrier.arrive.shared.b64 _, [%0];" :: "r"(a) : "memory");
}
__device__ __forceinline__ void mbar_wait(uint32_t a, int parity) {
    asm volatile(
        "{\n\t.reg .pred P;\n\t"
        "W%=:\n\t"
        "mbarrier.try_wait.parity.acquire.cta.shared::cta.b64 P, [%0], %1;\n\t"
        "@!P bra W%=;\n\t}"
        :: "r"(a), "r"(parity) : "memory");
}
__device__ __forceinline__ void bulk_g2s(uint32_t dst, const void* src,
                                         uint32_t bytes, uint32_t mbar) {
    asm volatile(
        "cp.async.bulk.shared::cta.global.mbarrier::complete_tx::bytes "
        "[%0], [%1], %2, [%3];"
        :: "r"(dst), "l"(src), "r"(bytes), "r"(mbar) : "memory");
}

// ---------------------------------------------------------------------------
// scatter: ONE red.global.add.noftz.v2.f16x2 (8B) per pin
// ---------------------------------------------------------------------------
__device__ __forceinline__ void scatter_pin(float sx, float sy, int net) {
    float epx = __expf(sx);
    float enx = __expf(-sx);
    float epy = __expf(sy);
    float eny = __expf(-sy);
    __half2 hx = __floats2half2_rn(epx, enx);
    __half2 hy = __floats2half2_rn(epy, eny);
    unsigned rx = *reinterpret_cast<unsigned*>(&hx);
    unsigned ry = *reinterpret_cast<unsigned*>(&hy);
    asm volatile("red.global.add.noftz.v2.f16x2 [%0], {%1, %2};"
                 :: "l"(&g_net_sums_h[net]), "r"(rx), "r"(ry)
                 : "memory");
}

// ---------------------------------------------------------------------------
// Pins: TMA(bulk)-fed double-buffered pipeline. Loads go GMEM->SMEM via the
// bulk path (UBLKCP), threads read via LDS -- the L1tex global wavefront
// queue is left almost exclusively to the REDG atomics.
// ---------------------------------------------------------------------------
__global__ void __launch_bounds__(256) pins_kernel_tma(
    const float* __restrict__ posx,
    const float* __restrict__ posy,
    const int*   __restrict__ pin2net,
    const float* __restrict__ gamma_ptr,
    float* __restrict__ out,
    int num_pins)
{
    __shared__ alignas(16) float s_px[STAGES][TILE];
    __shared__ alignas(16) float s_py[STAGES][TILE];
    __shared__ alignas(16) int   s_nn[STAGES][TILE];
    __shared__ alignas(8) unsigned long long s_full[STAGES];
    __shared__ alignas(8) unsigned long long s_empty[STAGES];

    int tid = threadIdx.x;
    if (blockIdx.x == 0 && tid == 0) *out = 0.f;

    uint32_t full_a[STAGES], empty_a[STAGES], px_a[STAGES], py_a[STAGES], nn_a[STAGES];
    #pragma unroll
    for (int s = 0; s < STAGES; s++) {
        full_a[s]  = smem_u32(&s_full[s]);
        empty_a[s] = smem_u32(&s_empty[s]);
        px_a[s]    = smem_u32(&s_px[s][0]);
        py_a[s]    = smem_u32(&s_py[s][0]);
        nn_a[s]    = smem_u32(&s_nn[s][0]);
    }

    if (tid == 0) {
        #pragma unroll
        for (int s = 0; s < STAGES; s++) {
            mbar_init(full_a[s], 1);      // producer's expect_tx arrival
            mbar_init(empty_a[s], 256);   // all consumers arrive
        }
    }
    __syncthreads();
    asm volatile("fence.proxy.async.shared::cta;" ::: "memory");

    int nfull = num_pins / TILE;            // full tiles handled by pipeline
    float inv_g = 1.0f / (*gamma_ptr);

    int ph_full[STAGES]  = {0, 0};   // consumer parity per stage
    int ph_empty[STAGES] = {1, 1};   // producer parity per stage (tid 0 only)

    const uint32_t TB = TILE * 4;    // 4096 bytes per array per tile

    // prologue: issue first STAGES tiles
    if (tid == 0) {
        #pragma unroll
        for (int k = 0; k < STAGES; k++) {
            long long t = (long long)blockIdx.x + (long long)k * gridDim.x;
            if (t < nfull) {
                mbar_wait(empty_a[k], ph_empty[k]); ph_empty[k] ^= 1;
                mbar_expect_tx(full_a[k], 3 * TB);
                bulk_g2s(px_a[k], posx   + t * TILE, TB, full_a[k]);
                bulk_g2s(py_a[k], posy   + t * TILE, TB, full_a[k]);
                bulk_g2s(nn_a[k], pin2net + t * TILE, TB, full_a[k]);
            }
        }
    }

    int j = 0;
    for (long long t = blockIdx.x; t < nfull; t += gridDim.x, j++) {
        int s = j & 1;
        mbar_wait(full_a[s], ph_full[s]); ph_full[s] ^= 1;

        // consume: 4 pins per thread via LDS.128
        float4 px = reinterpret_cast<const float4*>(s_px[s])[tid];
        float4 py = reinterpret_cast<const float4*>(s_py[s])[tid];
        int4   nn = reinterpret_cast<const int4*>(s_nn[s])[tid];

        scatter_pin(px.x * inv_g, py.x * inv_g, nn.x);
        scatter_pin(px.y * inv_g, py.y * inv_g, nn.y);
        scatter_pin(px.z * inv_g, py.z * inv_g, nn.z);
        scatter_pin(px.w * inv_g, py.w * inv_g, nn.w);

        mbar_arrive(empty_a[s]);

        if (tid == 0) {
            long long nt = t + 2LL * gridDim.x;
            if (nt < nfull) {
                mbar_wait(empty_a[s], ph_empty[s]); ph_empty[s] ^= 1;
                mbar_expect_tx(full_a[s], 3 * TB);
                bulk_g2s(px_a[s], posx   + nt * TILE, TB, full_a[s]);
                bulk_g2s(py_a[s], posy   + nt * TILE, TB, full_a[s]);
                bulk_g2s(nn_a[s], pin2net + nt * TILE, TB, full_a[s]);
            }
        }
    }

    // tail pins (num_pins % TILE) via direct loads, block 0 only
    if (blockIdx.x == 0) {
        for (int p = nfull * TILE + tid; p < num_pins; p += 256) {
            scatter_pin(__ldcs(&posx[p]) * inv_g, __ldcs(&posy[p]) * inv_g,
                        __ldcs(&pin2net[p]));
        }
    }
}

// ---------------------------------------------------------------------------
// Nets: grid-stride streaming reducer, 8 nets per iteration, all loads
// batched before stores/uses. log(a)+log(b)+log(c)+log(d) = log(a*b*c*d);
// the four sums of a net are zero together, so one prod>0 guard handles
// empty nets exactly. net_mask is int32 on device.
// ---------------------------------------------------------------------------
__device__ __forceinline__ float net_term(int m, unsigned rawx, unsigned rawy) {
    __half2 hx = *reinterpret_cast<__half2*>(&rawx);
    __half2 hy = *reinterpret_cast<__half2*>(&rawy);
    float spx = __low2float(hx);
    float snx = __high2float(hx);
    float spy = __low2float(hy);
    float sny = __high2float(hy);
    float prod = (spx * snx) * (spy * sny);
    return (m != 0 && prod > 0.f) ? __logf(prod) : 0.f;
}

__global__ void __launch_bounds__(256) nets_kernel_gs8(
    const int4*  __restrict__ mask4,
    const float* __restrict__ gamma_ptr,
    float* __restrict__ out,
    int num_octs,        // num_nets / 8
    int tail_start,      // num_octs * 8
    int num_nets)
{
    uint4* sums4 = reinterpret_cast<uint4*>(g_net_sums_h);  // 2 nets per uint4
    const uint4 z4 = make_uint4(0u, 0u, 0u, 0u);

    int tid    = blockIdx.x * blockDim.x + threadIdx.x;
    int stride = gridDim.x * blockDim.x;

    float v = 0.f;

    for (int i = tid; i < num_octs; i += stride) {
        uint4 s0 = sums4[4 * i];
        uint4 s1 = sums4[4 * i + 1];
        uint4 s2 = sums4[4 * i + 2];
        uint4 s3 = sums4[4 * i + 3];
        int4  m0 = __ldcs(&mask4[2 * i]);
        int4  m1 = __ldcs(&mask4[2 * i + 1]);

        v += net_term(m0.x, s0.x, s0.y);
        v += net_term(m0.y, s0.z, s0.w);
        v += net_term(m0.z, s1.x, s1.y);
        v += net_term(m0.w, s1.z, s1.w);
        v += net_term(m1.x, s2.x, s2.y);
        v += net_term(m1.y, s2.z, s2.w);
        v += net_term(m1.z, s3.x, s3.y);
        v += net_term(m1.w, s3.z, s3.w);

        sums4[4 * i]     = z4;          // reset for next launch
        sums4[4 * i + 1] = z4;
        sums4[4 * i + 2] = z4;
        sums4[4 * i + 3] = z4;
    }

    const int* mask1 = reinterpret_cast<const int*>(mask4);
    for (int n = tail_start + tid; n < num_nets; n += stride) {
        uint2 raw = g_net_sums_h[n];
        g_net_sums_h[n] = make_uint2(0u, 0u);
        v += net_term(mask1[n], raw.x, raw.y);
    }

    #pragma unroll
    for (int o = 16; o > 0; o >>= 1)
        v += __shfl_down_sync(0xFFFFFFFFu, v, o);

    __shared__ float sh[8];
    int lane = threadIdx.x & 31;
    int wid  = threadIdx.x >> 5;
    if (lane == 0) sh[wid] = v;
    __syncthreads();

    if (wid == 0) {
        float bv = (lane < 8) ? sh[lane] : 0.f;
        #pragma unroll
        for (int o = 4; o > 0; o >>= 1)
            bv += __shfl_down_sync(0xFFFFFFFFu, bv, o);
        if (lane == 0)
            atomicAdd(out, (*gamma_ptr) * bv);
    }
}

// ---------------------------------------------------------------------------
extern "C" void kernel_launch(void* const* d_in, const int* in_sizes, int n_in,
                              void* d_out, int out_size)
{
    const float* pos       = (const float*)d_in[0];   // [2 * num_pins]
    const int*   pin2net   = (const int*)d_in[1];     // [num_pins]
    const int*   net_mask  = (const int*)d_in[2];     // [num_nets] (bool as i32)
    const float* gamma_ptr = (const float*)d_in[3];   // scalar

    int num_pins = in_sizes[0] / 2;
    int num_nets = in_sizes[2];
    float* out = (float*)d_out;

    const int T = 256;

    // pins: TMA-fed pipeline, single-wave grid (8 blocks/SM x 148 SMs)
    int pblocks = 1184;
    pins_kernel_tma<<<pblocks, T>>>(
        pos, pos + num_pins, pin2net, gamma_ptr, out, num_pins);

    int num_net_octs = num_nets / 8;
    int tail_start_n = num_net_octs * 8;
    int nblocks = 1184;
    nets_kernel_gs8<<<nblocks, T>>>(
        (const int4*)net_mask, gamma_ptr, out,
        num_net_octs, tail_start_n, num_nets);
}

// round 11
// speedup vs baseline: 1.0886x; 1.0886x over previous
#include <cuda_runtime.h>
#include <cuda_fp16.h>
#include <cuda_bf16.h>
#include <cstdint>

#define NUM_NETS_MAX 2000000

// Per-net accumulators packed as 2x f16x2 in 8 bytes:
//   .x = half2{exp(+x/g), exp(-x/g)}, .y = half2{exp(+y/g), exp(-y/g)}
// Zero at module load; nets kernel re-zeroes after consuming each slot so
// every launch / graph replay starts from zeros.
__device__ uint2 g_net_sums_h[NUM_NETS_MAX];

// ---------------------------------------------------------------------------
// Pins: per-pin exp + scatter-add. 8 pins per thread; all 6 wide loads
// batched up front; __ldcs keeps the 120MB stream from displacing the 16MB
// L2-resident scratch. ONE red.global.add.noftz.v2.f16x2 (8B) per pin.
// Handles the (num_pins % 8) tail inline from the last thread.
// ---------------------------------------------------------------------------
__device__ __forceinline__ void scatter_pin(float sx, float sy, int net) {
    float epx = __expf(sx);
    float enx = __expf(-sx);
    float epy = __expf(sy);
    float eny = __expf(-sy);
    __half2 hx = __floats2half2_rn(epx, enx);
    __half2 hy = __floats2half2_rn(epy, eny);
    unsigned rx = *reinterpret_cast<unsigned*>(&hx);
    unsigned ry = *reinterpret_cast<unsigned*>(&hy);
    asm volatile("red.global.add.noftz.v2.f16x2 [%0], {%1, %2};"
                 :: "l"(&g_net_sums_h[net]), "r"(rx), "r"(ry)
                 : "memory");
}

__global__ void __launch_bounds__(256) pins_kernel_vec8(
    const float4* __restrict__ posx,
    const float4* __restrict__ posy,
    const int4*   __restrict__ pin2net,
    const float*  __restrict__ gamma_ptr,
    float* __restrict__ out,
    int num_octs,     // num_pins / 8
    int num_pins)
{
    int t = blockIdx.x * blockDim.x + threadIdx.x;
    if (t == 0) *out = 0.f;   // nets kernel (later in stream) accumulates into it

    float inv_g = 1.0f / (*gamma_ptr);

    if (t < num_octs) {
        int q0 = 2 * t;
        int q1 = 2 * t + 1;

        // batch all 6 wide loads before any use; evict-first (streaming)
        float4 px0 = __ldcs(&posx[q0]);
        float4 px1 = __ldcs(&posx[q1]);
        float4 py0 = __ldcs(&posy[q0]);
        float4 py1 = __ldcs(&posy[q1]);
        int4   n0  = __ldcs(&pin2net[q0]);
        int4   n1  = __ldcs(&pin2net[q1]);

        scatter_pin(px0.x * inv_g, py0.x * inv_g, n0.x);
        scatter_pin(px0.y * inv_g, py0.y * inv_g, n0.y);
        scatter_pin(px0.z * inv_g, py0.z * inv_g, n0.z);
        scatter_pin(px0.w * inv_g, py0.w * inv_g, n0.w);
        scatter_pin(px1.x * inv_g, py1.x * inv_g, n1.x);
        scatter_pin(px1.y * inv_g, py1.y * inv_g, n1.y);
        scatter_pin(px1.z * inv_g, py1.z * inv_g, n1.z);
        scatter_pin(px1.w * inv_g, py1.w * inv_g, n1.w);
    } else if (t == num_octs) {
        // tail pins (num_pins % 8), handled by one extra thread
        const float* fx = reinterpret_cast<const float*>(posx);
        const float* fy = reinterpret_cast<const float*>(posy);
        const int*   nn = reinterpret_cast<const int*>(pin2net);
        for (int p = num_octs * 8; p < num_pins; p++)
            scatter_pin(__ldcs(&fx[p]) * inv_g, __ldcs(&fy[p]) * inv_g,
                        __ldcs(&nn[p]));
    }
}

// ---------------------------------------------------------------------------
// Nets: grid-stride streaming reducer, 8 nets per iteration. ALL 6 loads
// batched before uses/stores (MLP). log(a)+log(b)+log(c)+log(d) =
// log(a*b*c*d); the four sums of a net are zero together (same pin set), so
// one prod>0 guard handles empty nets exactly. net_mask is int32 on device.
// ---------------------------------------------------------------------------
__device__ __forceinline__ float net_term(unsigned rawx, unsigned rawy) {
    __half2 hx = *reinterpret_cast<__half2*>(&rawx);
    __half2 hy = *reinterpret_cast<__half2*>(&rawy);
    float spx = __low2float(hx);
    float snx = __high2float(hx);
    float spy = __low2float(hy);
    float sny = __high2float(hy);
    float prod = (spx * snx) * (spy * sny);
    return (prod > 0.f) ? __logf(prod) : 0.f;
}

__global__ void __launch_bounds__(256) nets_kernel_gs8(
    const int4*  __restrict__ mask4,
    const float* __restrict__ gamma_ptr,
    float* __restrict__ out,
    int num_octs,        // num_nets / 8
    int tail_start,      // num_octs * 8
    int num_nets)
{
    uint4* sums4 = reinterpret_cast<uint4*>(g_net_sums_h);  // 2 nets per uint4
    const uint4 z4 = make_uint4(0u, 0u, 0u, 0u);

    int tid    = blockIdx.x * blockDim.x + threadIdx.x;
    int stride = gridDim.x * blockDim.x;

    float v = 0.f;

    for (int i = tid; i < num_octs; i += stride) {
        // ALL 6 loads batched before any use or store (max MLP)
        uint4 s0 = sums4[4 * i];        // nets 8i+0, 8i+1
        uint4 s1 = sums4[4 * i + 1];    // nets 8i+2, 8i+3
        uint4 s2 = sums4[4 * i + 2];    // nets 8i+4, 8i+5
        uint4 s3 = sums4[4 * i + 3];    // nets 8i+6, 8i+7
        int4  m0 = __ldcs(&mask4[2 * i]);
        int4  m1 = __ldcs(&mask4[2 * i + 1]);

        if (m0.x) v += net_term(s0.x, s0.y);
        if (m0.y) v += net_term(s0.z, s0.w);
        if (m0.z) v += net_term(s1.x, s1.y);
        if (m0.w) v += net_term(s1.z, s1.w);
        if (m1.x) v += net_term(s2.x, s2.y);
        if (m1.y) v += net_term(s2.z, s2.w);
        if (m1.z) v += net_term(s3.x, s3.y);
        if (m1.w) v += net_term(s3.z, s3.w);

        sums4[4 * i]     = z4;          // reset for next launch
        sums4[4 * i + 1] = z4;
        sums4[4 * i + 2] = z4;
        sums4[4 * i + 3] = z4;
    }

    // scalar tail (num_nets % 8)
    const int* mask1 = reinterpret_cast<const int*>(mask4);
    for (int n = tail_start + tid; n < num_nets; n += stride) {
        uint2 raw = g_net_sums_h[n];
        g_net_sums_h[n] = make_uint2(0u, 0u);
        if (mask1[n]) v += net_term(raw.x, raw.y);
    }

    // block reduce (once per block)
    #pragma unroll
    for (int o = 16; o > 0; o >>= 1)
        v += __shfl_down_sync(0xFFFFFFFFu, v, o);

    __shared__ float sh[8];
    int lane = threadIdx.x & 31;
    int wid  = threadIdx.x >> 5;
    if (lane == 0) sh[wid] = v;
    __syncthreads();

    if (wid == 0) {
        float bv = (lane < 8) ? sh[lane] : 0.f;
        #pragma unroll
        for (int o = 4; o > 0; o >>= 1)
            bv += __shfl_down_sync(0xFFFFFFFFu, bv, o);
        if (lane == 0)
            atomicAdd(out, (*gamma_ptr) * bv);
    }
}

// ---------------------------------------------------------------------------
extern "C" void kernel_launch(void* const* d_in, const int* in_sizes, int n_in,
                              void* d_out, int out_size)
{
    const float* pos       = (const float*)d_in[0];   // [2 * num_pins]
    const int*   pin2net   = (const int*)d_in[1];     // [num_pins]
    const int*   net_mask  = (const int*)d_in[2];     // [num_nets] (bool as i32)
    const float* gamma_ptr = (const float*)d_in[3];   // scalar

    int num_pins = in_sizes[0] / 2;
    int num_nets = in_sizes[2];
    float* out = (float*)d_out;

    const int T = 256;

    // Two launches total: pins (includes out=0 and tail), then nets.
    int num_pin_octs = num_pins / 8;
    int pthreads = num_pin_octs + 1;           // +1 thread for the tail
    int pb = (pthreads + T - 1) / T;
    pins_kernel_vec8<<<pb, T>>>(
        (const float4*)pos, (const float4*)(pos + num_pins),
        (const int4*)pin2net, gamma_ptr, out, num_pin_octs, num_pins);

    int num_net_octs = num_nets / 8;
    int tail_start_n = num_net_octs * 8;
    int nblocks = 1184;  // 8 blocks per SM on 148 SMs
    nets_kernel_gs8<<<nblocks, T>>>(
        (const int4*)net_mask, gamma_ptr, out,
        num_net_octs, tail_start_n, num_nets);
}